// round 2
// baseline (speedup 1.0000x reference)
#include <cuda_runtime.h>
#include <math.h>

#define H_   32
#define W_   32
#define P_   1024          // H*W
#define C_   768
#define C4_  192           // C/4
#define K9_  9
#define KK_  6912          // 9*C
#define KK4_ 1728          // KK/4
#define M_   4096          // N*P
#define NSEG 1406          // sum of 1x1 out-channels

// ---------------- scratch (static device allocations; no cudaMalloc) ----------
__device__ float g_big[(size_t)M_ * KK_];      // im2col / sampled-masked A (reused)
__device__ float g_om[(size_t)M_ * C_];        // conv3x3 output (per block, reused)
__device__ float g_blk[5][(size_t)M_ * C_];    // deform block outputs
__device__ float g_off[4 * 18 * P_];           // offsets [n][o][p]
__device__ float g_mask[4 * K9_ * P_];         // softmax, stored [n][p*9+k]
__device__ float g_BtConv[(size_t)KK_ * C_];   // conv_w transposed: [(k*768+c)][o]
__device__ float g_Bt1[C_ * NSEG];             // 1x1 weights transposed: [c][seg]
__device__ float g_scale[C_];
__device__ float g_shift[C_];

// ---------------- weight prep ------------------------------------------------
__global__ void tconv_k(const float* __restrict__ w) {
    size_t i = (size_t)blockIdx.x * 256 + threadIdx.x;
    if (i >= (size_t)KK_ * C_) return;
    int o  = (int)(i % C_);
    int kk = (int)(i / C_);
    int c  = kk % C_;
    int k  = kk / C_;
    g_BtConv[i] = w[((size_t)o * C_ + c) * 9 + k];
}

__global__ void t1x1_k(const float* __restrict__ w, int ch, int col0) {
    int i = blockIdx.x * 256 + threadIdx.x;
    if (i >= C_ * ch) return;
    int c = i / ch, j = i % ch;
    g_Bt1[c * NSEG + col0 + j] = w[j * C_ + c];
}

__global__ void bnprep_k(const float* g, const float* bt, const float* mu,
                         const float* var, const float* cb) {
    int c = blockIdx.x * 256 + threadIdx.x;
    if (c >= C_) return;
    float inv = g[c] / sqrtf(var[c] + 1e-5f);
    g_scale[c] = inv;
    g_shift[c] = cb[c] * inv + bt[c] - mu[c] * inv;
}

// ---------------- im2col for conv3x3 -----------------------------------------
__global__ void im2col_k(const float* __restrict__ x) {
    int p = blockIdx.x, k = blockIdx.y, n = blockIdx.z;
    int t = threadIdx.x;                      // 0..191 (float4 over channels)
    int h = p >> 5, w = p & 31;
    int hh = h + k / 3 - 1, ww = w + k % 3 - 1;
    float4 v = make_float4(0.f, 0.f, 0.f, 0.f);
    if (hh >= 0 && hh < H_ && ww >= 0 && ww < W_)
        v = ((const float4*)x)[((size_t)n * P_ + hh * W_ + ww) * C4_ + t];
    ((float4*)g_big)[((size_t)n * P_ + p) * KK4_ + k * C4_ + t] = v;
}

// ---------------- offset / mask heads (warp per pixel) -----------------------
__global__ void offsets_k(const float* __restrict__ ow, const float* __restrict__ mw) {
    int lane = threadIdx.x & 31;
    int row  = blockIdx.x * 8 + (threadIdx.x >> 5);   // 0..4095
    int n = row >> 10, p = row & 1023;
    const float* omr = g_om + (size_t)row * C_;
    float v[24];
#pragma unroll
    for (int i = 0; i < 24; i++) v[i] = omr[lane + 32 * i];
    float res[27];
#pragma unroll
    for (int o = 0; o < 27; o++) {
        const float* wr = (o < 18) ? (ow + o * C_) : (mw + (o - 18) * C_);
        float s = 0.f;
#pragma unroll
        for (int i = 0; i < 24; i++) s += v[i] * wr[lane + 32 * i];
#pragma unroll
        for (int d = 16; d; d >>= 1) s += __shfl_xor_sync(0xffffffffu, s, d);
        res[o] = s;
    }
    if (lane == 0) {
#pragma unroll
        for (int o = 0; o < 18; o++) g_off[n * (18 * P_) + o * P_ + p] = res[o];
        float mx = res[18];
#pragma unroll
        for (int k = 1; k < 9; k++) mx = fmaxf(mx, res[18 + k]);
        float e[9], sum = 0.f;
#pragma unroll
        for (int k = 0; k < 9; k++) { e[k] = expf(res[18 + k] - mx); sum += e[k]; }
        float r = 1.f / sum;
        // store softmax in NATURAL (h,w,k) layout: raw-reshape quirk handled at read
#pragma unroll
        for (int k = 0; k < 9; k++) g_mask[n * (K9_ * P_) + p * K9_ + k] = e[k] * r;
    }
}

// ---------------- deformable bilinear sampling * mask ------------------------
__global__ void sample_k(const float* __restrict__ x) {
    int p = blockIdx.x, k = blockIdx.y, n = blockIdx.z;
    int t = threadIdx.x;                      // 0..191
    float dy = g_off[n * (18 * P_) + (2 * k) * P_ + p];
    float dx = g_off[n * (18 * P_) + (2 * k + 1) * P_ + p];
    // raw-reshape quirk: mask[n,k,h,w] = natural-layout buffer at [n][k*1024+p]
    float m  = g_mask[n * (K9_ * P_) + k * P_ + p];
    int h = p >> 5, w = p & 31;
    float py = (float)(h - 1 + k / 3) + dy;
    float px = (float)(w - 1 + k % 3) + dx;
    float y0f = floorf(py), x0f = floorf(px);
    float wy = py - y0f, wx = px - x0f;
    int y0 = (int)y0f, x0 = (int)x0f;
    const float4* xb = (const float4*)x + (size_t)n * P_ * C4_;
    float w00 = (1.f - wy) * (1.f - wx), w01 = (1.f - wy) * wx;
    float w10 = wy * (1.f - wx),         w11 = wy * wx;
    bool vy0 = (y0 >= 0) && (y0 < H_),  vy1 = (y0 >= -1) && (y0 < H_ - 1);
    bool vx0 = (x0 >= 0) && (x0 < W_),  vx1 = (x0 >= -1) && (x0 < W_ - 1);
    float ax = 0.f, ay = 0.f, az = 0.f, aw = 0.f;
    if (vy0 && vx0) { float4 s = xb[(y0 * W_ + x0) * C4_ + t];
        ax += w00 * s.x; ay += w00 * s.y; az += w00 * s.z; aw += w00 * s.w; }
    if (vy0 && vx1) { float4 s = xb[(y0 * W_ + x0 + 1) * C4_ + t];
        ax += w01 * s.x; ay += w01 * s.y; az += w01 * s.z; aw += w01 * s.w; }
    if (vy1 && vx0) { float4 s = xb[((y0 + 1) * W_ + x0) * C4_ + t];
        ax += w10 * s.x; ay += w10 * s.y; az += w10 * s.z; aw += w10 * s.w; }
    if (vy1 && vx1) { float4 s = xb[((y0 + 1) * W_ + x0 + 1) * C4_ + t];
        ax += w11 * s.x; ay += w11 * s.y; az += w11 * s.z; aw += w11 * s.w; }
    float4 o;
    o.x = ax * m; o.y = ay * m; o.z = az * m; o.w = aw * m;
    ((float4*)g_big)[((size_t)n * P_ + p) * KK4_ + k * C4_ + t] = o;
}

// ---------------- generic fp32 SGEMM: C = A[M x K] * B[K x N(ldb)] -----------
// epilogue: optional bias[col], optional BN(scale/shift)+..., optional relu,
// optional accumulate into C; C column offset coff, leading dim ldc.
__global__ void __launch_bounds__(256) sgemm_k(
    const float* __restrict__ A, const float* __restrict__ B, float* __restrict__ C,
    int N, int K, int ldb, int bcol0, int ldc, int coff,
    const float* __restrict__ bias, int use_bn, int relu, int acc)
{
    __shared__ float As[8][128];
    __shared__ float Bs[8][128];
    int tid = threadIdx.x;
    int bm = blockIdx.y * 128, bn = blockIdx.x * 128;
    int arow = tid >> 1, acol = (tid & 1) * 4;
    int brow = tid >> 5, bcol = (tid & 31) * 4;
    int ty = tid >> 4, tx = tid & 15;
    float acc8[8][8];
#pragma unroll
    for (int i = 0; i < 8; i++)
#pragma unroll
        for (int j = 0; j < 8; j++) acc8[i][j] = 0.f;

    for (int k0 = 0; k0 < K; k0 += 8) {
        float4 a = *(const float4*)(A + (size_t)(bm + arow) * K + k0 + acol);
        As[acol + 0][arow] = a.x; As[acol + 1][arow] = a.y;
        As[acol + 2][arow] = a.z; As[acol + 3][arow] = a.w;
        const float* bp = B + (size_t)(k0 + brow) * ldb + bcol0 + bn + bcol;
        Bs[brow][bcol + 0] = (bn + bcol + 0 < N) ? bp[0] : 0.f;
        Bs[brow][bcol + 1] = (bn + bcol + 1 < N) ? bp[1] : 0.f;
        Bs[brow][bcol + 2] = (bn + bcol + 2 < N) ? bp[2] : 0.f;
        Bs[brow][bcol + 3] = (bn + bcol + 3 < N) ? bp[3] : 0.f;
        __syncthreads();
#pragma unroll
        for (int kk = 0; kk < 8; kk++) {
            float ar[8], br[8];
            *(float4*)ar       = *(const float4*)&As[kk][ty * 8];
            *(float4*)(ar + 4) = *(const float4*)&As[kk][ty * 8 + 4];
            *(float4*)br       = *(const float4*)&Bs[kk][tx * 8];
            *(float4*)(br + 4) = *(const float4*)&Bs[kk][tx * 8 + 4];
#pragma unroll
            for (int i = 0; i < 8; i++)
#pragma unroll
                for (int j = 0; j < 8; j++) acc8[i][j] += ar[i] * br[j];
        }
        __syncthreads();
    }
#pragma unroll
    for (int i = 0; i < 8; i++) {
        int row = bm + ty * 8 + i;
#pragma unroll
        for (int j = 0; j < 8; j++) {
            int col = bn + tx * 8 + j;
            if (col < N) {
                float v = acc8[i][j];
                if (bias)   v += bias[col];
                if (use_bn) v = v * g_scale[col] + g_shift[col];
                if (relu)   v = fmaxf(v, 0.f);
                size_t ci = (size_t)row * ldc + coff + col;
                if (acc) C[ci] += v; else C[ci] = v;
            }
        }
    }
}

// ---------------- residual ---------------------------------------------------
__global__ void resid_k(const float* __restrict__ x5, float* __restrict__ out) {
    size_t i = (size_t)blockIdx.x * 256 + threadIdx.x;
    if (i < (size_t)M_ * C_) out[i] += x5[i];
}

// ---------------- launch -----------------------------------------------------
extern "C" void kernel_launch(void* const* d_in, const int* in_sizes, int n_in,
                              void* d_out, int out_size) {
    static float* pBig = nullptr;
    static float* pOm = nullptr;
    static float* pBlk = nullptr;
    static float* pBtC = nullptr;
    static float* pBt1 = nullptr;
    if (!pBig) {
        cudaGetSymbolAddress((void**)&pBig, g_big);
        cudaGetSymbolAddress((void**)&pOm,  g_om);
        cudaGetSymbolAddress((void**)&pBlk, g_blk);
        cudaGetSymbolAddress((void**)&pBtC, g_BtConv);
        cudaGetSymbolAddress((void**)&pBt1, g_Bt1);
    }
    const float* x[5];
    for (int i = 0; i < 5; i++) x[i] = (const float*)d_in[i];
    const float* conv_w = (const float*)d_in[5];
    const float* conv_b = (const float*)d_in[6];
    const float* offw   = (const float*)d_in[7];
    const float* maskw  = (const float*)d_in[8];
    const float* gamma  = (const float*)d_in[9];
    const float* beta   = (const float*)d_in[10];
    const float* mean   = (const float*)d_in[11];
    const float* var    = (const float*)d_in[12];
    const float* w1x[8];
    for (int i = 0; i < 8; i++) w1x[i] = (const float*)d_in[13 + i];
    float* out = (float*)d_out;

    // weight prep (cheap, runs inside the graph each replay — deterministic)
    tconv_k<<<(int)(((size_t)KK_ * C_ + 255) / 256), 256>>>(conv_w);
    const int chs[8]  = {30, 100, 150, 150, 220, 220, 268, 268};
    const int bcol[8] = {0, 30, 130, 280, 430, 650, 870, 1138};
    for (int i = 0; i < 8; i++)
        t1x1_k<<<(C_ * chs[i] + 255) / 256, 256>>>(w1x[i], chs[i], bcol[i]);
    bnprep_k<<<3, 256>>>(gamma, beta, mean, var, conv_b);

    dim3 gIm(P_, K9_, 4);
    for (int b = 0; b < 5; b++) {
        im2col_k<<<gIm, 192>>>(x[b]);
        sgemm_k<<<dim3(6, 32), 256>>>(pBig, pBtC, pOm,
                                      C_, KK_, C_, 0, C_, 0, conv_b, 0, 0, 0);
        offsets_k<<<512, 256>>>(offw, maskw);
        sample_k<<<gIm, 192>>>(x[b]);
        sgemm_k<<<dim3(6, 32), 256>>>(pBig, pBtC, pBlk + (size_t)b * M_ * C_,
                                      C_, KK_, C_, 0, C_, 0, nullptr, 1, 1, 0);
    }

    // 1x1 segment convs into d_out (concat layout), plus raw-input branches
    const int coffs[5] = {0, 30, 130, 280, 500};
    const int waIdx[5] = {0, 1, 2, 4, 6};
    for (int b = 0; b < 5; b++) {
        int wi = waIdx[b];
        int n = chs[wi];
        sgemm_k<<<dim3((n + 127) / 128, 32), 256>>>(
            pBlk + (size_t)b * M_ * C_, pBt1, out,
            n, C_, NSEG, bcol[wi], C_, coffs[b], nullptr, 0, 0, 0);
        if (b >= 2) {
            int wj = wi + 1;
            sgemm_k<<<dim3((n + 127) / 128, 32), 256>>>(
                x[b], pBt1, out,
                n, C_, NSEG, bcol[wj], C_, coffs[b], nullptr, 0, 0, 1);
        }
    }
    resid_k<<<(int)(((size_t)M_ * C_ + 255) / 256), 256>>>(x[4], out);
}

// round 4
// speedup vs baseline: 3.4843x; 3.4843x over previous
#include <cuda_runtime.h>
#include <cuda_bf16.h>
#include <math.h>
#include <stdint.h>

typedef unsigned short u16;
typedef uint32_t u32;
typedef uint64_t u64;

#define C_    768
#define P_    1024
#define K3BIG 20736          // 27 * 768  (9 taps x 3 split-slots x 768)
#define K3FIN 4608           // [blk 2304 | x 2304]
#define MBIG  20480
#define TM    128
#define TN    256
#define KT    64
#define THREADS 512
#define STG_BYTES 49152      // A 16KB + B 32KB
#define DYN_SMEM (3 * STG_BYTES)

// ---------------- static scratch ---------------------------------------------
__device__ u16  g_A1[(size_t)MBIG * K3BIG];
__device__ u16  g_A2[(size_t)5 * 4096 * K3FIN];
__device__ u16  g_B1[(size_t)C_ * K3BIG];
__device__ u16  g_Bfin[(size_t)5 * 512 * K3FIN];
__device__ float g_om[(size_t)MBIG * C_];
__device__ float g_off[20 * 18 * P_];
__device__ float g_mask[20 * 9 * P_];
__device__ float g_scale[C_], g_shift[C_];

struct X5  { const float* p[5]; };
struct W10 { const float* a[5]; const float* b[5]; };

// ---------------- helpers ----------------------------------------------------
__device__ __forceinline__ void split2(float v, u16& h, u16& l) {
    __nv_bfloat16 hb = __float2bfloat16(v);
    h = __bfloat16_as_ushort(hb);
    l = __bfloat16_as_ushort(__float2bfloat16(v - __bfloat162float(hb)));
}
__device__ __forceinline__ u32 s2u(const void* p) {
    return (u32)__cvta_generic_to_shared(p);
}
__device__ __forceinline__ void cpa16(u32 s, const void* g) {
    asm volatile("cp.async.cg.shared.global [%0], [%1], 16;"
                 :: "r"(s), "l"((u64)__cvta_generic_to_global((void*)g)));
}
#define CP_COMMIT() asm volatile("cp.async.commit_group;")
#define CP_WAIT1()  asm volatile("cp.async.wait_group 1;")
#define SWZ(o) ((o) ^ (((o) >> 3) & 0x70))

#define LDSM4(r0, r1, r2, r3, addr) \
    asm volatile("ldmatrix.sync.aligned.m8n8.x4.shared.b16 {%0,%1,%2,%3}, [%4];" \
        : "=r"(r0), "=r"(r1), "=r"(r2), "=r"(r3) : "r"(addr))

#define MMA16816(d, a0, a1, a2, a3, b0, b1) \
    asm volatile("mma.sync.aligned.m16n8k16.row.col.f32.bf16.bf16.f32 " \
        "{%0,%1,%2,%3}, {%4,%5,%6,%7}, {%8,%9}, {%0,%1,%2,%3};" \
        : "+f"((d)[0]), "+f"((d)[1]), "+f"((d)[2]), "+f"((d)[3]) \
        : "r"(a0), "r"(a1), "r"(a2), "r"(a3), "r"(b0), "r"(b1))

// ---------------- weight / BN prep -------------------------------------------
__global__ void bconv_k(const float* __restrict__ w) {
    size_t i = (size_t)blockIdx.x * 256 + threadIdx.x;
    if (i >= (size_t)C_ * C_ * 9) return;
    int k = (int)(i % 9);
    size_t t = i / 9;
    int c = (int)(t % C_), o = (int)(t / C_);
    u16 h, l; split2(w[i], h, l);
    u16* dst = g_B1 + (size_t)o * K3BIG + (size_t)k * 2304 + c;
    dst[0] = h; dst[768] = h; dst[1536] = l;       // B slots [Bh, Bh, Bl]
}

__global__ void bfin_k(W10 ws) {
    size_t i = (size_t)blockIdx.x * 256 + threadIdx.x;
    if (i >= (size_t)5 * 512 * 1536) return;
    int cc = (int)(i % 1536);
    size_t t = i / 1536;
    int j = (int)(t % 512), b = (int)(t / 512);
    int half = cc / 768, c = cc % 768;
    const int CH[5] = {30, 100, 150, 220, 268};
    float v = 0.f;
    if (j < CH[b]) {
        if (half == 0) v = ws.a[b][j * C_ + c];
        else if (b >= 2) v = ws.b[b][j * C_ + c];
    }
    u16 h, l; split2(v, h, l);
    u16* dst = g_Bfin + ((size_t)b * 512 + j) * K3FIN + half * 2304 + c;
    dst[0] = h; dst[768] = h; dst[1536] = l;
}

__global__ void bnprep_k(const float* g, const float* bt, const float* mu,
                         const float* var, const float* cb) {
    int c = blockIdx.x * 256 + threadIdx.x;
    if (c >= C_) return;
    float inv = g[c] / sqrtf(var[c] + 1e-5f);
    g_scale[c] = inv;
    g_shift[c] = cb[c] * inv + bt[c] - mu[c] * inv;
}

// ---------------- A writers (192 threads, 4 channels each, coalesced) --------
__device__ __forceinline__ void store_split4(u32* base32, int tid, float4 v,
                                             int aside) {
    u16 h0, l0, h1, l1, h2, l2, h3, l3;
    split2(v.x, h0, l0); split2(v.y, h1, l1);
    split2(v.z, h2, l2); split2(v.w, h3, l3);
    u32 h01 = (u32)h0 | ((u32)h1 << 16), h23 = (u32)h2 | ((u32)h3 << 16);
    u32 l01 = (u32)l0 | ((u32)l1 << 16), l23 = (u32)l2 | ((u32)l3 << 16);
    // aside: slots [Ah, Al, Ah]; (B-side would be [h,h,l], unused here)
    base32[2 * tid] = h01;       base32[2 * tid + 1] = h23;
    base32[384 + 2 * tid] = l01; base32[385 + 2 * tid] = l23;
    base32[768 + 2 * tid] = h01; base32[769 + 2 * tid] = h23;
    (void)aside;
}

__global__ void im2col_split_k(X5 xs) {
    int p = blockIdx.x, k = blockIdx.y, z = blockIdx.z;   // z = b*4+n
    int b = z >> 2, n = z & 3;
    int h = p >> 5, w = p & 31;
    int hh = h + k / 3 - 1, ww = w + k % 3 - 1;
    bool ok = hh >= 0 && hh < 32 && ww >= 0 && ww < 32;
    float4 v = make_float4(0.f, 0.f, 0.f, 0.f);
    if (ok)
        v = ((const float4*)(xs.p[b] + (size_t)(n * P_ + hh * 32 + ww) * C_))[threadIdx.x];
    size_t row = (size_t)z * P_ + p;
    u32* base32 = (u32*)(g_A1 + row * K3BIG + (size_t)k * 2304);
    store_split4(base32, threadIdx.x, v, 1);
}

__global__ void xsplit_k(X5 xs) {
    int row = blockIdx.x, b = blockIdx.y + 2;
    float4 v = ((const float4*)(xs.p[b] + (size_t)row * C_))[threadIdx.x];
    u32* base32 = (u32*)(g_A2 + ((size_t)b * 4096 + row) * K3FIN + 2304);
    store_split4(base32, threadIdx.x, v, 1);
}

// ---------------- offset / mask heads ----------------------------------------
__global__ void offsets_k(const float* __restrict__ ow, const float* __restrict__ mw) {
    int lane = threadIdx.x & 31;
    int row = blockIdx.x * 8 + (threadIdx.x >> 5);
    const float* omr = g_om + (size_t)row * C_;
    float v[24];
#pragma unroll
    for (int i = 0; i < 24; i++) v[i] = omr[lane + 32 * i];
    float res[27];
#pragma unroll
    for (int o = 0; o < 27; o++) {
        const float* wr = (o < 18) ? (ow + o * C_) : (mw + (o - 18) * C_);
        float s = 0.f;
#pragma unroll
        for (int i = 0; i < 24; i++) s += v[i] * wr[lane + 32 * i];
#pragma unroll
        for (int d = 16; d; d >>= 1) s += __shfl_xor_sync(0xffffffffu, s, d);
        res[o] = s;
    }
    if (lane == 0) {
        int z = row >> 10, p = row & 1023;
#pragma unroll
        for (int o = 0; o < 18; o++) g_off[z * 18 * P_ + o * P_ + p] = res[o];
        float mx = res[18];
#pragma unroll
        for (int k = 1; k < 9; k++) mx = fmaxf(mx, res[18 + k]);
        float e[9], sum = 0.f;
#pragma unroll
        for (int k = 0; k < 9; k++) { e[k] = expf(res[18 + k] - mx); sum += e[k]; }
        float r = 1.f / sum;
#pragma unroll
        for (int k = 0; k < 9; k++) g_mask[z * 9 * P_ + p * 9 + k] = e[k] * r;
    }
}

// ---------------- deformable sampling ----------------------------------------
__global__ void sample_split_k(X5 xs) {
    int p = blockIdx.x, k = blockIdx.y, z = blockIdx.z;
    int b = z >> 2;
    float dy = g_off[z * 18 * P_ + (2 * k) * P_ + p];
    float dx = g_off[z * 18 * P_ + (2 * k + 1) * P_ + p];
    float m = g_mask[z * 9 * P_ + k * P_ + p];            // raw-reshape quirk
    int h = p >> 5, w = p & 31;
    float py = (float)(h - 1 + k / 3) + dy;
    float px = (float)(w - 1 + k % 3) + dx;
    float y0f = floorf(py), x0f = floorf(px);
    float wy = py - y0f, wx = px - x0f;
    int y0 = (int)y0f, x0 = (int)x0f;
    float w00 = (1.f - wy) * (1.f - wx), w01 = (1.f - wy) * wx;
    float w10 = wy * (1.f - wx),         w11 = wy * wx;
    bool vy0 = (y0 >= 0) && (y0 < 32),  vy1 = (y0 >= -1) && (y0 < 31);
    bool vx0 = (x0 >= 0) && (x0 < 32),  vx1 = (x0 >= -1) && (x0 < 31);
    const float4* xb = (const float4*)(xs.p[b] + (size_t)(z & 3) * P_ * C_);
    int t = threadIdx.x;
    float4 a = make_float4(0.f, 0.f, 0.f, 0.f);
    if (vy0 && vx0) { float4 s = xb[(size_t)(y0 * 32 + x0) * 192 + t];
        a.x += w00 * s.x; a.y += w00 * s.y; a.z += w00 * s.z; a.w += w00 * s.w; }
    if (vy0 && vx1) { float4 s = xb[(size_t)(y0 * 32 + x0 + 1) * 192 + t];
        a.x += w01 * s.x; a.y += w01 * s.y; a.z += w01 * s.z; a.w += w01 * s.w; }
    if (vy1 && vx0) { float4 s = xb[(size_t)((y0 + 1) * 32 + x0) * 192 + t];
        a.x += w10 * s.x; a.y += w10 * s.y; a.z += w10 * s.z; a.w += w10 * s.w; }
    if (vy1 && vx1) { float4 s = xb[(size_t)((y0 + 1) * 32 + x0 + 1) * 192 + t];
        a.x += w11 * s.x; a.y += w11 * s.y; a.z += w11 * s.z; a.w += w11 * s.w; }
    a.x *= m; a.y *= m; a.z *= m; a.w *= m;
    size_t row = (size_t)z * P_ + p;
    u32* base32 = (u32*)(g_A1 + row * K3BIG + (size_t)k * 2304);
    store_split4(base32, t, a, 1);
}

// ---------------- mma.sync bf16 GEMM: D[128x256] = A * B^T -------------------
// mode 0: g_om[row][col] = D + aux[col]
// mode 1: t = relu(D*scale+shift); split-bf16 into g_A2 (blk half)
// mode 2: out[row][coff+col] = D + aux[row*768+coff+col], col < chN
__global__ void __launch_bounds__(THREADS, 1) gemm_mma(
    const u16* __restrict__ A, const u16* __restrict__ B,
    long lda, long ldb, int NK, int mode,
    const float* __restrict__ aux, float* __restrict__ outp, int chN, int coff)
{
    extern __shared__ char sm[];
    u32 sbase = s2u(sm);
    const int tid = threadIdx.x;
    const int wid = tid >> 5, lane = tid & 31;
    const int wm = wid >> 2, wn = wid & 3;
    const int m0 = blockIdx.y * TM, n0 = blockIdx.x * TN;

    const char* Abase = (const char*)(A + (size_t)m0 * lda);
    const char* Bbase = (const char*)(B + (size_t)n0 * ldb);
    const long ldab = lda * 2, ldbb = ldb * 2;

    auto loadStage = [&](int s, int kc) {
        u32 ab = sbase + s * STG_BYTES;
        const char* Ag = Abase + (size_t)kc * 128;
#pragma unroll
        for (int it = 0; it < 2; it++) {
            int i = it * THREADS + tid;             // 0..1023
            int row = i >> 3, c16 = i & 7;
            u32 off = (u32)(row * 128 + c16 * 16);
            cpa16(ab + SWZ(off), Ag + (size_t)row * ldab + c16 * 16);
        }
        u32 bb = ab + 16384;
        const char* Bg = Bbase + (size_t)kc * 128;
#pragma unroll
        for (int it = 0; it < 4; it++) {
            int i = it * THREADS + tid;             // 0..2047
            int row = i >> 3, c16 = i & 7;
            u32 off = (u32)(row * 128 + c16 * 16);
            cpa16(bb + SWZ(off), Bg + (size_t)row * ldbb + c16 * 16);
        }
        CP_COMMIT();
    };

    float acc[2][8][4];
#pragma unroll
    for (int i = 0; i < 2; i++)
#pragma unroll
        for (int j = 0; j < 8; j++)
#pragma unroll
            for (int q = 0; q < 4; q++) acc[i][j][q] = 0.f;

    loadStage(0, 0);
    loadStage(1, 1);

    for (int kc = 0; kc < NK; kc++) {
        CP_WAIT1();
        __syncthreads();
        u32 ab = sbase + (kc % 3) * STG_BYTES;
        u32 bb = ab + 16384;
#pragma unroll
        for (int ks = 0; ks < 4; ks++) {
            u32 afr[2][4];
#pragma unroll
            for (int ms = 0; ms < 2; ms++) {
                int row = wm * 32 + ms * 16 + (lane & 15);
                u32 off = (u32)(row * 128 + ks * 32 + (lane >> 4) * 16);
                LDSM4(afr[ms][0], afr[ms][1], afr[ms][2], afr[ms][3], ab + SWZ(off));
            }
#pragma unroll
            for (int np = 0; np < 4; np++) {
                int g = lane >> 3;
                int row = wn * 64 + np * 16 + ((g >> 1) & 1) * 8 + (lane & 7);
                u32 off = (u32)(row * 128 + ks * 32 + (g & 1) * 16);
                u32 bfr[4];
                LDSM4(bfr[0], bfr[1], bfr[2], bfr[3], bb + SWZ(off));
#pragma unroll
                for (int ms = 0; ms < 2; ms++) {
                    MMA16816(acc[ms][2 * np], afr[ms][0], afr[ms][1], afr[ms][2],
                             afr[ms][3], bfr[0], bfr[1]);
                    MMA16816(acc[ms][2 * np + 1], afr[ms][0], afr[ms][1], afr[ms][2],
                             afr[ms][3], bfr[2], bfr[3]);
                }
            }
        }
        __syncthreads();
        int kl = kc + 2;
        if (kl < NK) loadStage(kl % 3, kl);
        else CP_COMMIT();
    }

    // epilogue
    int quad = lane >> 2, qt = lane & 3;
#pragma unroll
    for (int ms = 0; ms < 2; ms++) {
#pragma unroll
        for (int ns = 0; ns < 8; ns++) {
            int colb = n0 + wn * 64 + ns * 8 + 2 * qt;
#pragma unroll
            for (int hh = 0; hh < 2; hh++) {
                int row = m0 + wm * 32 + ms * 16 + quad + hh * 8;
                float v0 = acc[ms][ns][2 * hh], v1 = acc[ms][ns][2 * hh + 1];
                if (mode == 0) {
                    g_om[(size_t)row * C_ + colb]     = v0 + aux[colb];
                    g_om[(size_t)row * C_ + colb + 1] = v1 + aux[colb + 1];
                } else if (mode == 1) {
                    float t0 = fmaxf(v0 * g_scale[colb] + g_shift[colb], 0.f);
                    float t1 = fmaxf(v1 * g_scale[colb + 1] + g_shift[colb + 1], 0.f);
                    u16 h0, l0, h1, l1;
                    split2(t0, h0, l0); split2(t1, h1, l1);
                    u32* p32 = (u32*)(g_A2 + (size_t)row * K3FIN);
                    int ci = colb >> 1;
                    p32[ci]       = (u32)h0 | ((u32)h1 << 16);
                    p32[384 + ci] = (u32)l0 | ((u32)l1 << 16);
                    p32[768 + ci] = (u32)h0 | ((u32)h1 << 16);
                } else {
                    if (colb < chN)
                        outp[(size_t)row * C_ + coff + colb] =
                            v0 + aux[(size_t)row * C_ + coff + colb];
                    if (colb + 1 < chN)
                        outp[(size_t)row * C_ + coff + colb + 1] =
                            v1 + aux[(size_t)row * C_ + coff + colb + 1];
                }
            }
        }
    }
}

// ---------------- launch -----------------------------------------------------
extern "C" void kernel_launch(void* const* d_in, const int* in_sizes, int n_in,
                              void* d_out, int out_size) {
    static u16 *pA1 = 0, *pA2 = 0, *pB1 = 0, *pBf = 0;
    if (!pA1) {
        cudaGetSymbolAddress((void**)&pA1, g_A1);
        cudaGetSymbolAddress((void**)&pA2, g_A2);
        cudaGetSymbolAddress((void**)&pB1, g_B1);
        cudaGetSymbolAddress((void**)&pBf, g_Bfin);
        cudaFuncSetAttribute(gemm_mma, cudaFuncAttributeMaxDynamicSharedMemorySize,
                             DYN_SMEM);
    }
    X5 xs;
    for (int i = 0; i < 5; i++) xs.p[i] = (const float*)d_in[i];
    const float* conv_w = (const float*)d_in[5];
    const float* conv_b = (const float*)d_in[6];
    const float* offw   = (const float*)d_in[7];
    const float* maskw  = (const float*)d_in[8];
    W10 ws;
    const int waIdx[5] = {0, 1, 2, 4, 6};
    for (int b = 0; b < 5; b++) {
        ws.a[b] = (const float*)d_in[13 + waIdx[b]];
        ws.b[b] = (b >= 2) ? (const float*)d_in[13 + waIdx[b] + 1] : ws.a[b];
    }
    float* out = (float*)d_out;

    bconv_k<<<(int)(((size_t)C_ * C_ * 9 + 255) / 256), 256>>>(conv_w);
    bfin_k<<<(int)(((size_t)5 * 512 * 1536 + 255) / 256), 256>>>(ws);
    bnprep_k<<<3, 256>>>((const float*)d_in[9], (const float*)d_in[10],
                         (const float*)d_in[11], (const float*)d_in[12], conv_b);
    xsplit_k<<<dim3(4096, 3), 192>>>(xs);

    dim3 gS(P_, 9, 20);
    im2col_split_k<<<gS, 192>>>(xs);
    gemm_mma<<<dim3(3, 160), THREADS, DYN_SMEM>>>(pA1, pB1, K3BIG, K3BIG, 324, 0,
                                                  conv_b, nullptr, 0, 0);
    offsets_k<<<2560, 256>>>(offw, maskw);
    sample_split_k<<<gS, 192>>>(xs);
    gemm_mma<<<dim3(3, 160), THREADS, DYN_SMEM>>>(pA1, pB1, K3BIG, K3BIG, 324, 1,
                                                  nullptr, nullptr, 0, 0);

    const int CH[5]   = {30, 100, 150, 220, 268};
    const int COFF[5] = {0, 30, 130, 280, 500};
    for (int b = 0; b < 5; b++) {
        int nt = (CH[b] + 255) / 256;
        int nk = (b < 2) ? 36 : 72;
        gemm_mma<<<dim3(nt, 32), THREADS, DYN_SMEM>>>(
            pA2 + (size_t)b * 4096 * K3FIN, pBf + (size_t)b * 512 * K3FIN,
            K3FIN, K3FIN, nk, 2, xs.p[4], out, CH[b], COFF[b]);
    }
}